// round 16
// baseline (speedup 1.0000x reference)
#include <cuda_runtime.h>
#include <cuda_bf16.h>
#include <stdint.h>
#include <math.h>

#define NH   16
#define NKV  8
#define D    128
#define HID  2048
#define QKV_N ((NH + 2 * NKV) * D)   /* 4096 */
#define MAXT 2048

/* ---------------- scratch (no allocations allowed) ---------------- */
__device__ float g_invfreq[D / 2];
__device__ float g_cos[(size_t)MAXT * 64];
__device__ float g_sin[(size_t)MAXT * 64];

/* split-bf16 operands (weights kept K-major; no transposes) */
__device__ __nv_bfloat16 g_ah  [(size_t)MAXT * HID];
__device__ __nv_bfloat16 g_al  [(size_t)MAXT * HID];
__device__ __nv_bfloat16 g_wq_h[(size_t)HID * QKV_N];
__device__ __nv_bfloat16 g_wq_l[(size_t)HID * QKV_N];
__device__ __nv_bfloat16 g_wo_h[(size_t)HID * HID];
__device__ __nv_bfloat16 g_wo_l[(size_t)HID * HID];

/* attention operands / outputs (all compensated bf16 splits) */
__device__ __nv_bfloat16 g_qh[(size_t)MAXT * NH  * D];
__device__ __nv_bfloat16 g_ql[(size_t)MAXT * NH  * D];
__device__ __nv_bfloat16 g_kh[(size_t)MAXT * NKV * D];
__device__ __nv_bfloat16 g_kl[(size_t)MAXT * NKV * D];
__device__ __nv_bfloat16 g_vh[(size_t)MAXT * NKV * D];
__device__ __nv_bfloat16 g_vl[(size_t)MAXT * NKV * D];
__device__ __nv_bfloat16 g_oth[(size_t)MAXT * NH * D];
__device__ __nv_bfloat16 g_otl[(size_t)MAXT * NH * D];

/* ================= helpers ========================================= */
__device__ __forceinline__ uint32_t smem_u32(const void* p) {
    uint32_t a;
    asm("{ .reg .u64 t; cvta.to.shared.u64 t, %1; cvt.u32.u64 %0, t; }"
        : "=r"(a) : "l"(p));
    return a;
}

#define CP_ASYNC16(dst, src)                                                   \
    asm volatile("cp.async.cg.shared.global [%0], [%1], 16;"                   \
        :: "r"(dst), "l"(src))
#define CP_COMMIT() asm volatile("cp.async.commit_group;" ::: "memory")
#define CP_WAIT(n)  asm volatile("cp.async.wait_group %0;" :: "n"(n) : "memory")

#define LDSM_X4(r0, r1, r2, r3, addr)                                          \
    asm volatile("ldmatrix.sync.aligned.m8n8.x4.shared.b16 {%0,%1,%2,%3}, [%4];" \
        : "=r"(r0), "=r"(r1), "=r"(r2), "=r"(r3) : "r"(addr))

#define LDSM_X4_T(r0, r1, r2, r3, addr)                                        \
    asm volatile("ldmatrix.sync.aligned.m8n8.x4.trans.shared.b16 {%0,%1,%2,%3}, [%4];" \
        : "=r"(r0), "=r"(r1), "=r"(r2), "=r"(r3) : "r"(addr))

#define MMA16816(d, a0, a1, a2, a3, b0, b1)                                    \
    asm volatile("mma.sync.aligned.m16n8k16.row.col.f32.bf16.bf16.f32 "        \
        "{%0,%1,%2,%3}, {%4,%5,%6,%7}, {%8,%9}, {%0,%1,%2,%3};"                \
        : "+f"((d)[0]), "+f"((d)[1]), "+f"((d)[2]), "+f"((d)[3])               \
        : "r"(a0), "r"(a1), "r"(a2), "r"(a3), "r"(b0), "r"(b1))

__device__ __forceinline__ uint32_t packbf(float lo, float hi) {
    uint32_t r;
    asm("cvt.rn.bf16x2.f32 %0, %1, %2;" : "=r"(r) : "f"(hi), "f"(lo));
    return r;
}

/* ================= GEMM mainloop (shared) =========================== */
#define KC      32
#define TILE_B  8192
#define STAGE_B (4 * TILE_B)
#define NSTAGE  3
#define GSM_TOTAL (NSTAGE * STAGE_B)   /* 96 KB */

__device__ __forceinline__ uint32_t tile_off(int r, int s) {
    return (uint32_t)((r & 63) * 128 + (((s | ((r >> 6) << 2)) ^ (r & 7)) << 4));
}

__device__ __forceinline__ void gemm_mainloop(
    const __nv_bfloat16* __restrict__ Ah, const __nv_bfloat16* __restrict__ Al,
    const __nv_bfloat16* __restrict__ Bh, const __nv_bfloat16* __restrict__ Bl,
    int N, int K, int m0, int n0, uint32_t sb, float acc[4][4][4])
{
    const int tid = threadIdx.x;
    const int wid = tid >> 5;
    const int lid = tid & 31;
    const int mw  = wid & 1;
    const int nw  = wid >> 1;

    const int r0 = tid >> 2;
    const int sg = tid & 3;
    const size_t rskip = (size_t)64 * K;
    const __nv_bfloat16* pAh = Ah + (size_t)(m0 + r0) * K + sg * 8;
    const __nv_bfloat16* pAl = Al + (size_t)(m0 + r0) * K + sg * 8;
    const uint32_t dA0 = tile_off(r0, sg);
    const uint32_t dA1 = tile_off(r0 + 64, sg);

    const int rb = tid >> 3;
    const int s1 = tid & 7;
    const __nv_bfloat16* pBh = Bh + (size_t)rb * N + n0 + s1 * 8;
    const __nv_bfloat16* pBl = Bl + (size_t)rb * N + n0 + s1 * 8;
    const uint32_t dB0 = (uint32_t)(rb * 256 + (((s1)     ^ (rb & 7)) << 4));
    const uint32_t dB1 = (uint32_t)(rb * 256 + (((s1 + 8) ^ (rb & 7)) << 4));

    const int nch = K / KC;

#define GEMM_LOAD_STAGE(stg, cidx) do {                                        \
        uint32_t _b = sb + (stg) * STAGE_B;                                    \
        size_t _ka = (size_t)(cidx) * KC;                                      \
        size_t _kb = (size_t)(cidx) * KC * N;                                  \
        CP_ASYNC16(_b + 0 * TILE_B + dA0, pAh + _ka);                          \
        CP_ASYNC16(_b + 0 * TILE_B + dA1, pAh + _ka + rskip);                  \
        CP_ASYNC16(_b + 1 * TILE_B + dA0, pAl + _ka);                          \
        CP_ASYNC16(_b + 1 * TILE_B + dA1, pAl + _ka + rskip);                  \
        CP_ASYNC16(_b + 2 * TILE_B + dB0, pBh + _kb);                          \
        CP_ASYNC16(_b + 2 * TILE_B + dB1, pBh + _kb + 64);                     \
        CP_ASYNC16(_b + 3 * TILE_B + dB0, pBl + _kb);                          \
        CP_ASYNC16(_b + 3 * TILE_B + dB1, pBl + _kb + 64);                     \
        CP_COMMIT();                                                           \
    } while (0)

    GEMM_LOAD_STAGE(0, 0);
    if (nch > 1) GEMM_LOAD_STAGE(1, 1);

    int st = 0;
    for (int c = 0; c < nch; c++) {
        if (c + 2 < nch) {
            GEMM_LOAD_STAGE((st + 2) % NSTAGE, c + 2);
            CP_WAIT(2);
        } else if (c + 1 < nch) {
            CP_WAIT(1);
        } else {
            CP_WAIT(0);
        }
        __syncthreads();

        const uint32_t tAh = sb + st * STAGE_B + 0 * TILE_B;
        const uint32_t tAl = sb + st * STAGE_B + 1 * TILE_B;
        const uint32_t tBh = sb + st * STAGE_B + 2 * TILE_B;
        const uint32_t tBl = sb + st * STAGE_B + 3 * TILE_B;

#pragma unroll
        for (int kb = 0; kb < KC / 16; kb++) {
            const int sseg = 2 * kb + (lid >> 4);
            uint32_t ah[4][4], al[4][4];
#pragma unroll
            for (int mf = 0; mf < 4; mf++) {
                int r = mw * 64 + mf * 16 + (lid & 15);
                uint32_t off = tile_off(r, sseg);
                LDSM_X4(ah[mf][0], ah[mf][1], ah[mf][2], ah[mf][3], tAh + off);
                LDSM_X4(al[mf][0], al[mf][1], al[mf][2], al[mf][3], tAl + off);
            }
            uint32_t bh[4][2], bl[4][2];
            {
                int br = kb * 16 + (lid & 7) + 8 * ((lid >> 3) & 1);
                uint32_t brow = (uint32_t)(br * 256);
                uint32_t bx   = (uint32_t)(br & 7) << 4;
#pragma unroll
                for (int nb = 0; nb < 2; nb++) {
                    uint32_t bs = (uint32_t)(nw * 4 + 2 * nb + (lid >> 4)) << 4;
                    uint32_t boff = brow + (bs ^ bx);
                    uint32_t b0, b1, b2, b3;
                    LDSM_X4_T(b0, b1, b2, b3, tBh + boff);
                    bh[2 * nb + 0][0] = b0; bh[2 * nb + 0][1] = b1;
                    bh[2 * nb + 1][0] = b2; bh[2 * nb + 1][1] = b3;
                    LDSM_X4_T(b0, b1, b2, b3, tBl + boff);
                    bl[2 * nb + 0][0] = b0; bl[2 * nb + 0][1] = b1;
                    bl[2 * nb + 1][0] = b2; bl[2 * nb + 1][1] = b3;
                }
            }
#pragma unroll
            for (int mf = 0; mf < 4; mf++)
#pragma unroll
                for (int j = 0; j < 4; j++)
                    MMA16816(acc[mf][j], ah[mf][0], ah[mf][1], ah[mf][2], ah[mf][3],
                             bh[j][0], bh[j][1]);
#pragma unroll
            for (int mf = 0; mf < 4; mf++)
#pragma unroll
                for (int j = 0; j < 4; j++)
                    MMA16816(acc[mf][j], ah[mf][0], ah[mf][1], ah[mf][2], ah[mf][3],
                             bl[j][0], bl[j][1]);
#pragma unroll
            for (int mf = 0; mf < 4; mf++)
#pragma unroll
                for (int j = 0; j < 4; j++)
                    MMA16816(acc[mf][j], al[mf][0], al[mf][1], al[mf][2], al[mf][3],
                             bh[j][0], bh[j][1]);
        }
        __syncthreads();
        st = (st + 1) % NSTAGE;
    }
}

/* ================= plain GEMM (out projection) ===================== */
__global__ __launch_bounds__(256, 2) void tc_gemm(
    const __nv_bfloat16* __restrict__ Ah, const __nv_bfloat16* __restrict__ Al,
    const __nv_bfloat16* __restrict__ Bh, const __nv_bfloat16* __restrict__ Bl,
    float* __restrict__ C, int M, int N, int K)
{
    extern __shared__ char smem[];
    const uint32_t sb = smem_u32(smem);
    const int lid = threadIdx.x & 31;
    const int wid = threadIdx.x >> 5;
    const int mw  = wid & 1;
    const int nw  = wid >> 1;
    const int m0  = blockIdx.y * 128;
    const int n0  = blockIdx.x * 128;

    float acc[4][4][4];
#pragma unroll
    for (int i = 0; i < 4; i++)
#pragma unroll
        for (int j = 0; j < 4; j++)
#pragma unroll
            for (int u = 0; u < 4; u++) acc[i][j][u] = 0.f;

    gemm_mainloop(Ah, Al, Bh, Bl, N, K, m0, n0, sb, acc);

#pragma unroll
    for (int mf = 0; mf < 4; mf++) {
        int rbase = m0 + mw * 64 + mf * 16 + (lid >> 2);
#pragma unroll
        for (int j = 0; j < 4; j++) {
            int col = n0 + nw * 32 + j * 8 + 2 * (lid & 3);
            *(float2*)&C[(size_t)rbase * N + col] =
                make_float2(acc[mf][j][0], acc[mf][j][1]);
            *(float2*)&C[(size_t)(rbase + 8) * N + col] =
                make_float2(acc[mf][j][2], acc[mf][j][3]);
        }
    }
}

/* ================= QKV GEMM with fused RMSNorm+RoPE+split ========== */
__global__ __launch_bounds__(256, 2) void tc_gemm_qkv(
    const __nv_bfloat16* __restrict__ Ah, const __nv_bfloat16* __restrict__ Al,
    const __nv_bfloat16* __restrict__ Bh, const __nv_bfloat16* __restrict__ Bl,
    const float* __restrict__ q_norm_w, const float* __restrict__ k_norm_w,
    int K)
{
    extern __shared__ char smem[];
    const uint32_t sb = smem_u32(smem);
    const int lid = threadIdx.x & 31;
    const int wid = threadIdx.x >> 5;
    const int mw  = wid & 1;
    const int nw  = wid >> 1;
    const int hidx = blockIdx.x;
    const int m0  = blockIdx.y * 128;
    const int n0  = hidx * 128;

    float acc[4][4][4];
#pragma unroll
    for (int i = 0; i < 4; i++)
#pragma unroll
        for (int j = 0; j < 4; j++)
#pragma unroll
            for (int u = 0; u < 4; u++) acc[i][j][u] = 0.f;

    gemm_mainloop(Ah, Al, Bh, Bl, QKV_N, K, m0, n0, sb, acc);

    const int cb = nw * 32 + 2 * (lid & 3);

    if (hidx >= NH + NKV) {
        const int hv = hidx - NH - NKV;
#pragma unroll
        for (int mf = 0; mf < 4; mf++) {
            int t0 = m0 + mw * 64 + mf * 16 + (lid >> 2);
#pragma unroll
            for (int j = 0; j < 4; j++) {
                int c = cb + j * 8;
                float a0 = acc[mf][j][0], a1 = acc[mf][j][1];
                float b0 = acc[mf][j][2], b1 = acc[mf][j][3];
                __nv_bfloat16 h0 = __float2bfloat16(a0), h1 = __float2bfloat16(a1);
                __nv_bfloat16 g0 = __float2bfloat16(b0), g1 = __float2bfloat16(b1);
                size_t iA = ((size_t)t0 * NKV + hv) * D + c;
                size_t iB = ((size_t)(t0 + 8) * NKV + hv) * D + c;
                *(uint32_t*)(g_vh + iA) = packbf(a0, a1);
                *(uint32_t*)(g_vl + iA) = packbf(a0 - __bfloat162float(h0),
                                                 a1 - __bfloat162float(h1));
                *(uint32_t*)(g_vh + iB) = packbf(b0, b1);
                *(uint32_t*)(g_vl + iB) = packbf(b0 - __bfloat162float(g0),
                                                 b1 - __bfloat162float(g1));
            }
        }
        return;
    }

    float* ssq  = (float*)smem;
    float* tile = (float*)smem + 512;

#pragma unroll
    for (int mf = 0; mf < 4; mf++) {
        float s0 = 0.f, s1 = 0.f;
#pragma unroll
        for (int j = 0; j < 4; j++) {
            s0 += acc[mf][j][0] * acc[mf][j][0] + acc[mf][j][1] * acc[mf][j][1];
            s1 += acc[mf][j][2] * acc[mf][j][2] + acc[mf][j][3] * acc[mf][j][3];
        }
        s0 += __shfl_xor_sync(0xFFFFFFFFu, s0, 1);
        s0 += __shfl_xor_sync(0xFFFFFFFFu, s0, 2);
        s1 += __shfl_xor_sync(0xFFFFFFFFu, s1, 1);
        s1 += __shfl_xor_sync(0xFFFFFFFFu, s1, 2);
        if ((lid & 3) == 0) {
            int rl = mw * 64 + mf * 16 + (lid >> 2);
            ssq[rl * 4 + nw] = s0;
            ssq[(rl + 8) * 4 + nw] = s1;
        }
    }
    __syncthreads();

    const float* w = (hidx < NH) ? q_norm_w : k_norm_w;
    float wv[4][2];
#pragma unroll
    for (int j = 0; j < 4; j++) {
        wv[j][0] = w[cb + j * 8];
        wv[j][1] = w[cb + j * 8 + 1];
    }
#pragma unroll
    for (int mf = 0; mf < 4; mf++) {
        int rl0 = mw * 64 + mf * 16 + (lid >> 2);
        int rl1 = rl0 + 8;
        float v0 = ssq[rl0 * 4 + 0] + ssq[rl0 * 4 + 1] + ssq[rl0 * 4 + 2] + ssq[rl0 * 4 + 3];
        float v1 = ssq[rl1 * 4 + 0] + ssq[rl1 * 4 + 1] + ssq[rl1 * 4 + 2] + ssq[rl1 * 4 + 3];
        float ri0 = rsqrtf(v0 * (1.f / (float)D) + 1e-6f);
        float ri1 = rsqrtf(v1 * (1.f / (float)D) + 1e-6f);
#pragma unroll
        for (int j = 0; j < 4; j++) {
            int c = cb + j * 8;
            tile[rl0 * 132 + c]     = acc[mf][j][0] * ri0 * wv[j][0];
            tile[rl0 * 132 + c + 1] = acc[mf][j][1] * ri0 * wv[j][1];
            tile[rl1 * 132 + c]     = acc[mf][j][2] * ri1 * wv[j][0];
            tile[rl1 * 132 + c + 1] = acc[mf][j][3] * ri1 * wv[j][1];
        }
    }
    __syncthreads();

    const float sc = (hidx < NH) ? 0.08838834764831845f : 1.0f;
#pragma unroll
    for (int mf = 0; mf < 4; mf++) {
#pragma unroll
        for (int half = 0; half < 2; half++) {
            int rl = mw * 64 + mf * 16 + (lid >> 2) + half * 8;
            int t  = m0 + rl;
#pragma unroll
            for (int j = 0; j < 4; j++) {
                int c = cb + j * 8;
                float y[2];
#pragma unroll
                for (int u = 0; u < 2; u++) {
                    int cc = c + u;
                    int dm = cc & 63;
                    float x = tile[rl * 132 + cc];
                    float p = tile[rl * 132 + (cc ^ 64)];
                    float cs = g_cos[(size_t)t * 64 + dm];
                    float sn = g_sin[(size_t)t * 64 + dm];
                    y[u] = (cc < 64) ? (x * cs - p * sn) : (x * cs + p * sn);
                    y[u] *= sc;
                }
                __nv_bfloat16 h0 = __float2bfloat16(y[0]);
                __nv_bfloat16 h1 = __float2bfloat16(y[1]);
                uint32_t hw = packbf(y[0], y[1]);
                uint32_t lw = packbf(y[0] - __bfloat162float(h0),
                                     y[1] - __bfloat162float(h1));
                if (hidx < NH) {
                    size_t o = ((size_t)t * NH + hidx) * D + c;
                    *(uint32_t*)(g_qh + o) = hw;
                    *(uint32_t*)(g_ql + o) = lw;
                } else {
                    size_t o = ((size_t)t * NKV + (hidx - NH)) * D + c;
                    *(uint32_t*)(g_kh + o) = hw;
                    *(uint32_t*)(g_kl + o) = lw;
                }
            }
        }
    }
}

/* ================= split conversion (straight) ===================== */
__global__ __launch_bounds__(256) void cvt_split(const float* __restrict__ x,
                                                 __nv_bfloat16* __restrict__ h,
                                                 __nv_bfloat16* __restrict__ l,
                                                 int n)
{
    int i = (blockIdx.x * 256 + threadIdx.x) * 4;
    if (i >= n) return;
    float4 v = *(const float4*)(x + i);
    float vv[4] = {v.x, v.y, v.z, v.w};
    __nv_bfloat16 hh[4], ll[4];
#pragma unroll
    for (int j = 0; j < 4; j++) {
        hh[j] = __float2bfloat16(vv[j]);
        ll[j] = __float2bfloat16(vv[j] - __bfloat162float(hh[j]));
    }
    *(uint2*)(h + i) = *(uint2*)hh;
    *(uint2*)(l + i) = *(uint2*)ll;
}

/* ---------------- trig tables --------------------------------------- */
__global__ void init_freq()
{
    int d = threadIdx.x;
    g_invfreq[d] = (float)(1.0 / pow(1000000.0, (double)d / (double)(D / 2)));
}

__global__ void init_trig(const int* __restrict__ positions)
{
    int t = blockIdx.x;
    int d = threadIdx.x;
    float ang = (float)positions[t] * g_invfreq[d];
    g_cos[(size_t)t * 64 + d] = cosf(ang);
    g_sin[(size_t)t * 64 + d] = sinf(ang);
}

/* ---------------- causal flash attention (GQA-merged) ---------------
   One CTA = (m-block, kv-head): 8 warps, warps 0-3 -> q-head 2hk,
   warps 4-7 -> q-head 2hk+1. K/V double-buffered, loaded ONCE per
   tile for both heads. smem: Q 2x32KB + 2 KV stages x 64KB = 192KB. */
#define AT_KV0   65536
#define AT_KVST  65536
#define ASM_TOTAL (65536 + 2 * 65536)   /* 192 KB */

__global__ __launch_bounds__(256) void attn_kernel(int T_)
{
    extern __shared__ char asmem[];
    const uint32_t sb = smem_u32(asmem);

    const int hk  = blockIdx.y;
    const int bi  = gridDim.x - 1 - blockIdx.x;    /* heavy first */
    const int m0  = bi * 64;
    const int tid = threadIdx.x;
    const int wid = tid >> 5;
    const int lid = tid & 31;
    const int wq   = wid >> 2;          /* which q head of the pair */
    const int wrow = (wid & 3) * 16;    /* row group within 64      */
    const int h    = 2 * hk + wq;

    /* loader lane mapping: rows r = lr + it*16, segs ls */
    const int lr = tid >> 4;            /* 0..15 */
    const int ls = tid & 15;
    const uint32_t ldst = (uint32_t)(lr * 256 + ((ls ^ (lr & 7)) << 4));
    const size_t itq  = (size_t)16 * NH * D;
    const size_t itkv = (size_t)16 * NKV * D;

    /* Q tiles for both heads (group 0) */
#pragma unroll
    for (int hd = 0; hd < 2; hd++) {
        size_t gq = ((size_t)(m0 + lr) * NH + (2 * hk + hd)) * D + ls * 8;
#pragma unroll
        for (int it = 0; it < 4; it++) {
            uint32_t off = ldst + it * 4096;
            size_t g = gq + it * itq;
            CP_ASYNC16(sb + hd * 32768 + off, g_qh + g);
            CP_ASYNC16(sb + hd * 32768 + 16384 + off, g_ql + g);
        }
    }
    CP_COMMIT();

    const int ntiles = bi + 1;
    const size_t kvgb = ((size_t)lr * NKV + hk) * D + ls * 8;

    /* KV tile 0 into stage 0 (group 1) */
    {
        uint32_t stb = sb + AT_KV0;
#pragma unroll
        for (int it = 0; it < 4; it++) {
            uint32_t off = ldst + it * 4096;
            size_t g = kvgb + it * itkv;
            CP_ASYNC16(stb + 0     + off, g_kh + g);
            CP_ASYNC16(stb + 16384 + off, g_kl + g);
            CP_ASYNC16(stb + 32768 + off, g_vh + g);
            CP_ASYNC16(stb + 49152 + off, g_vl + g);
        }
    }
    CP_COMMIT();

    const uint32_t qbh = sb + wq * 32768;
    const uint32_t qbl = qbh + 16384;

    float o[16][4];
#pragma unroll
    for (int i = 0; i < 16; i++)
#pragma unroll
        for (int u = 0; u < 4; u++) o[i][u] = 0.f;

    const int r0g = m0 + wrow + (lid >> 2);
    const int r1g = r0g + 8;
    float mrow0 = -1e30f, mrow1 = -1e30f;
    float lsum0 = 0.f, lsum1 = 0.f;

    for (int kt = 0; kt < ntiles; kt++) {
        const int k0 = kt * 64;
        const int st = kt & 1;
        if (kt + 1 < ntiles) {
            uint32_t stb = sb + AT_KV0 + (st ^ 1) * AT_KVST;
            const size_t gb = kvgb + (size_t)(k0 + 64) * NKV * D;
#pragma unroll
            for (int it = 0; it < 4; it++) {
                uint32_t off = ldst + it * 4096;
                size_t g = gb + it * itkv;
                CP_ASYNC16(stb + 0     + off, g_kh + g);
                CP_ASYNC16(stb + 16384 + off, g_kl + g);
                CP_ASYNC16(stb + 32768 + off, g_vh + g);
                CP_ASYNC16(stb + 49152 + off, g_vl + g);
            }
            CP_COMMIT();
            CP_WAIT(1);
        } else {
            CP_WAIT(0);
        }
        __syncthreads();

        const uint32_t tKH = sb + AT_KV0 + st * AT_KVST + 0;
        const uint32_t tKL = tKH + 16384;
        const uint32_t tVH = tKH + 32768;
        const uint32_t tVL = tKH + 49152;

        /* ---- S = Q K^T ---- */
        float sa[8][4];
#pragma unroll
        for (int nb = 0; nb < 8; nb++)
#pragma unroll
            for (int u = 0; u < 4; u++) sa[nb][u] = 0.f;

#pragma unroll
        for (int kb = 0; kb < 8; kb++) {
            int qr = wrow + (lid & 15);
            int qs = 2 * kb + (lid >> 4);
            uint32_t qoff = (uint32_t)(qr * 256 + ((qs ^ (qr & 7)) << 4));
            uint32_t qh0, qh1, qh2, qh3, ql0, ql1, ql2, ql3;
            LDSM_X4(qh0, qh1, qh2, qh3, qbh + qoff);
            LDSM_X4(ql0, ql1, ql2, ql3, qbl + qoff);

            uint32_t kh[4][4], kl[4][4];
#pragma unroll
            for (int nb16 = 0; nb16 < 4; nb16++) {
                int kr = nb16 * 16 + (lid & 15);
                int ks = 2 * kb + (lid >> 4);
                uint32_t koff = (uint32_t)(kr * 256 + ((ks ^ (kr & 7)) << 4));
                LDSM_X4(kh[nb16][0], kh[nb16][1], kh[nb16][2], kh[nb16][3], tKH + koff);
                LDSM_X4(kl[nb16][0], kl[nb16][1], kl[nb16][2], kl[nb16][3], tKL + koff);
            }
#pragma unroll
            for (int nb16 = 0; nb16 < 4; nb16++) {
                MMA16816(sa[2 * nb16 + 0], qh0, qh1, qh2, qh3, kh[nb16][0], kh[nb16][2]);
                MMA16816(sa[2 * nb16 + 1], qh0, qh1, qh2, qh3, kh[nb16][1], kh[nb16][3]);
            }
#pragma unroll
            for (int nb16 = 0; nb16 < 4; nb16++) {
                MMA16816(sa[2 * nb16 + 0], qh0, qh1, qh2, qh3, kl[nb16][0], kl[nb16][2]);
                MMA16816(sa[2 * nb16 + 1], qh0, qh1, qh2, qh3, kl[nb16][1], kl[nb16][3]);
            }
#pragma unroll
            for (int nb16 = 0; nb16 < 4; nb16++) {
                MMA16816(sa[2 * nb16 + 0], ql0, ql1, ql2, ql3, kh[nb16][0], kh[nb16][2]);
                MMA16816(sa[2 * nb16 + 1], ql0, ql1, ql2, ql3, kh[nb16][1], kh[nb16][3]);
            }
        }

        /* ---- mask + online softmax ---- */
        float mx0 = mrow0, mx1 = mrow1;
#pragma unroll
        for (int nb = 0; nb < 8; nb++) {
            int col = k0 + nb * 8 + 2 * (lid & 3);
            if (col > r0g)     sa[nb][0] = -1e30f;
            if (col + 1 > r0g) sa[nb][1] = -1e30f;
            if (col > r1g)     sa[nb][2] = -1e30f;
            if (col + 1 > r1g) sa[nb][3] = -1e30f;
            mx0 = fmaxf(mx0, fmaxf(sa[nb][0], sa[nb][1]));
            mx1 = fmaxf(mx1, fmaxf(sa[nb][2], sa[nb][3]));
        }
        mx0 = fmaxf(mx0, __shfl_xor_sync(0xFFFFFFFFu, mx0, 1));
        mx0 = fmaxf(mx0, __shfl_xor_sync(0xFFFFFFFFu, mx0, 2));
        mx1 = fmaxf(mx1, __shfl_xor_sync(0xFFFFFFFFu, mx1, 1));
        mx1 = fmaxf(mx1, __shfl_xor_sync(0xFFFFFFFFu, mx1, 2));

        float corr0 = __expf(mrow0 - mx0);
        float corr1 = __expf(mrow1 - mx1);
        mrow0 = mx0; mrow1 = mx1;

        float ps0 = 0.f, ps1 = 0.f;
#pragma unroll
        for (int nb = 0; nb < 8; nb++) {
            sa[nb][0] = __expf(sa[nb][0] - mx0);
            sa[nb][1] = __expf(sa[nb][1] - mx0);
            sa[nb][2] = __expf(sa[nb][2] - mx1);
            sa[nb][3] = __expf(sa[nb][3] - mx1);
            ps0 += sa[nb][0] + sa[nb][1];
            ps1 += sa[nb][2] + sa[nb][3];
        }
        ps0 += __shfl_xor_sync(0xFFFFFFFFu, ps0, 1);
        ps0 += __shfl_xor_sync(0xFFFFFFFFu, ps0, 2);
        ps1 += __shfl_xor_sync(0xFFFFFFFFu, ps1, 1);
        ps1 += __shfl_xor_sync(0xFFFFFFFFu, ps1, 2);
        lsum0 = lsum0 * corr0 + ps0;
        lsum1 = lsum1 * corr1 + ps1;

#pragma unroll
        for (int i = 0; i < 16; i++) {
            o[i][0] *= corr0; o[i][1] *= corr0;
            o[i][2] *= corr1; o[i][3] *= corr1;
        }

        /* ---- O += P V ---- */
#pragma unroll
        for (int jb = 0; jb < 4; jb++) {
            float p00 = sa[2 * jb][0],     p01 = sa[2 * jb][1];
            float p02 = sa[2 * jb][2],     p03 = sa[2 * jb][3];
            float p10 = sa[2 * jb + 1][0], p11 = sa[2 * jb + 1][1];
            float p12 = sa[2 * jb + 1][2], p13 = sa[2 * jb + 1][3];
            uint32_t ph0 = packbf(p00, p01), ph1 = packbf(p02, p03);
            uint32_t ph2 = packbf(p10, p11), ph3 = packbf(p12, p13);
            uint32_t pl0 = packbf(p00 - __bfloat162float(__float2bfloat16(p00)),
                                  p01 - __bfloat162float(__float2bfloat16(p01)));
            uint32_t pl1 = packbf(p02 - __bfloat162float(__float2bfloat16(p02)),
                                  p03 - __bfloat162float(__float2bfloat16(p03)));
            uint32_t pl2 = packbf(p10 - __bfloat162float(__float2bfloat16(p10)),
                                  p11 - __bfloat162float(__float2bfloat16(p11)));
            uint32_t pl3 = packbf(p12 - __bfloat162float(__float2bfloat16(p12)),
                                  p13 - __bfloat162float(__float2bfloat16(p13)));

            int m = lid >> 3;
            int vr = jb * 16 + (lid & 7) + 8 * (m & 1);
#pragma unroll
            for (int dp = 0; dp < 4; dp++) {
                int dn0 = 2 * dp, dn1 = 2 * dp + 1;
                int vs0 = 2 * dn0 + (m >> 1);
                int vs1 = 2 * dn1 + (m >> 1);
                uint32_t voff0 = (uint32_t)(vr * 256 + ((vs0 ^ (vr & 7)) << 4));
                uint32_t voff1 = (uint32_t)(vr * 256 + ((vs1 ^ (vr & 7)) << 4));
                uint32_t vA[4], vB[4], wA[4], wB[4];
                LDSM_X4_T(vA[0], vA[1], vA[2], vA[3], tVH + voff0);
                LDSM_X4_T(vB[0], vB[1], vB[2], vB[3], tVH + voff1);
                LDSM_X4_T(wA[0], wA[1], wA[2], wA[3], tVL + voff0);
                LDSM_X4_T(wB[0], wB[1], wB[2], wB[3], tVL + voff1);
                MMA16816(o[2 * dn0 + 0], ph0, ph1, ph2, ph3, vA[0], vA[1]);
                MMA16816(o[2 * dn0 + 1], ph0, ph1, ph2, ph3, vA[2], vA[3]);
                MMA16816(o[2 * dn1 + 0], ph0, ph1, ph2, ph3, vB[0], vB[1]);
                MMA16816(o[2 * dn1 + 1], ph0, ph1, ph2, ph3, vB[2], vB[3]);
                MMA16816(o[2 * dn0 + 0], ph0, ph1, ph2, ph3, wA[0], wA[1]);
                MMA16816(o[2 * dn0 + 1], ph0, ph1, ph2, ph3, wA[2], wA[3]);
                MMA16816(o[2 * dn1 + 0], ph0, ph1, ph2, ph3, wB[0], wB[1]);
                MMA16816(o[2 * dn1 + 1], ph0, ph1, ph2, ph3, wB[2], wB[3]);
                MMA16816(o[2 * dn0 + 0], pl0, pl1, pl2, pl3, vA[0], vA[1]);
                MMA16816(o[2 * dn0 + 1], pl0, pl1, pl2, pl3, vA[2], vA[3]);
                MMA16816(o[2 * dn1 + 0], pl0, pl1, pl2, pl3, vB[0], vB[1]);
                MMA16816(o[2 * dn1 + 1], pl0, pl1, pl2, pl3, vB[2], vB[3]);
            }
        }
        __syncthreads();   /* all reads of stage st done before refill */
    }

    /* epilogue: normalize, split to bf16 h/l, store */
    const float inv0 = 1.f / lsum0;
    const float inv1 = 1.f / lsum1;
#pragma unroll
    for (int dn = 0; dn < 16; dn++) {
        int col = dn * 8 + 2 * (lid & 3);
        float a0 = o[dn][0] * inv0, a1 = o[dn][1] * inv0;
        float b0 = o[dn][2] * inv1, b1 = o[dn][3] * inv1;
        __nv_bfloat16 ha0 = __float2bfloat16(a0), ha1 = __float2bfloat16(a1);
        __nv_bfloat16 hb0 = __float2bfloat16(b0), hb1 = __float2bfloat16(b1);
        uint32_t hA = packbf(a0, a1);
        uint32_t lA = packbf(a0 - __bfloat162float(ha0), a1 - __bfloat162float(ha1));
        uint32_t hB = packbf(b0, b1);
        uint32_t lB = packbf(b0 - __bfloat162float(hb0), b1 - __bfloat162float(hb1));
        size_t iA = (size_t)r0g * (NH * D) + h * D + col;
        size_t iB = (size_t)r1g * (NH * D) + h * D + col;
        *(uint32_t*)(g_oth + iA) = hA;
        *(uint32_t*)(g_otl + iA) = lA;
        *(uint32_t*)(g_oth + iB) = hB;
        *(uint32_t*)(g_otl + iB) = lB;
    }
}

/* ---------------- launch -------------------------------------------- */
extern "C" void kernel_launch(void* const* d_in, const int* in_sizes, int n_in,
                              void* d_out, int out_size)
{
    const int*   positions = (const int*)d_in[0];
    const float* hidden    = (const float*)d_in[1];
    const float* w_qkv     = (const float*)d_in[2];
    const float* q_norm_w  = (const float*)d_in[3];
    const float* k_norm_w  = (const float*)d_in[4];
    const float* w_o       = (const float*)d_in[5];
    float*       out       = (float*)d_out;
    const int    T         = in_sizes[0];   /* 2048 */

    __nv_bfloat16 *ah, *al, *wqh, *wql, *oh, *ol, *woh, *wol;
    cudaGetSymbolAddress((void**)&ah,  g_ah);
    cudaGetSymbolAddress((void**)&al,  g_al);
    cudaGetSymbolAddress((void**)&wqh, g_wq_h);
    cudaGetSymbolAddress((void**)&wql, g_wq_l);
    cudaGetSymbolAddress((void**)&oh,  g_oth);
    cudaGetSymbolAddress((void**)&ol,  g_otl);
    cudaGetSymbolAddress((void**)&woh, g_wo_h);
    cudaGetSymbolAddress((void**)&wol, g_wo_l);

    cudaFuncSetAttribute(tc_gemm, cudaFuncAttributeMaxDynamicSharedMemorySize, GSM_TOTAL);
    cudaFuncSetAttribute(tc_gemm_qkv, cudaFuncAttributeMaxDynamicSharedMemorySize, GSM_TOTAL);
    cudaFuncSetAttribute(attn_kernel, cudaFuncAttributeMaxDynamicSharedMemorySize, ASM_TOTAL);

    /* 0) trig tables + straight splits */
    init_freq<<<1, D / 2>>>();
    init_trig<<<T, 64>>>(positions);
    cvt_split<<<(T * HID) / 1024, 256>>>(hidden, ah, al, T * HID);
    cvt_split<<<(HID * QKV_N) / 1024, 256>>>(w_qkv, wqh, wql, HID * QKV_N);

    /* 1) QKV projection + fused RMSNorm/RoPE/split */
    {
        dim3 g(QKV_N / 128, T / 128);
        tc_gemm_qkv<<<g, 256, GSM_TOTAL>>>(ah, al, wqh, wql,
                                           q_norm_w, k_norm_w, HID);
    }

    /* 2) causal GQA flash attention (merged head pairs) */
    dim3 g3(T / 64, NKV);
    attn_kernel<<<g3, 256, ASM_TOTAL>>>(T);

    /* 3) output projection */
    cvt_split<<<(HID * HID) / 1024, 256>>>(w_o, woh, wol, HID * HID);
    {
        dim3 g(HID / 128, T / 128);
        tc_gemm<<<g, 256, GSM_TOTAL>>>(oh, ol, woh, wol, out, T, HID, HID);
    }
}

// round 17
// speedup vs baseline: 1.0235x; 1.0235x over previous
#include <cuda_runtime.h>
#include <cuda_bf16.h>
#include <stdint.h>
#include <math.h>

#define NH   16
#define NKV  8
#define D    128
#define HID  2048
#define QKV_N ((NH + 2 * NKV) * D)   /* 4096 */
#define MAXT 2048

/* ---------------- scratch (no allocations allowed) ---------------- */
__device__ float g_invfreq[D / 2];
__device__ float g_cos[(size_t)MAXT * 64];
__device__ float g_sin[(size_t)MAXT * 64];

/* split-bf16 operands (weights kept K-major; no transposes) */
__device__ __nv_bfloat16 g_ah  [(size_t)MAXT * HID];
__device__ __nv_bfloat16 g_al  [(size_t)MAXT * HID];
__device__ __nv_bfloat16 g_wq_h[(size_t)HID * QKV_N];
__device__ __nv_bfloat16 g_wq_l[(size_t)HID * QKV_N];
__device__ __nv_bfloat16 g_wo_h[(size_t)HID * HID];
__device__ __nv_bfloat16 g_wo_l[(size_t)HID * HID];

/* attention operands / outputs (all compensated bf16 splits) */
__device__ __nv_bfloat16 g_qh[(size_t)MAXT * NH  * D];
__device__ __nv_bfloat16 g_ql[(size_t)MAXT * NH  * D];
__device__ __nv_bfloat16 g_kh[(size_t)MAXT * NKV * D];
__device__ __nv_bfloat16 g_kl[(size_t)MAXT * NKV * D];
__device__ __nv_bfloat16 g_vh[(size_t)MAXT * NKV * D];
__device__ __nv_bfloat16 g_vl[(size_t)MAXT * NKV * D];
__device__ __nv_bfloat16 g_oth[(size_t)MAXT * NH * D];
__device__ __nv_bfloat16 g_otl[(size_t)MAXT * NH * D];

/* ================= helpers ========================================= */
__device__ __forceinline__ uint32_t smem_u32(const void* p) {
    uint32_t a;
    asm("{ .reg .u64 t; cvta.to.shared.u64 t, %1; cvt.u32.u64 %0, t; }"
        : "=r"(a) : "l"(p));
    return a;
}

#define CP_ASYNC16(dst, src)                                                   \
    asm volatile("cp.async.cg.shared.global [%0], [%1], 16;"                   \
        :: "r"(dst), "l"(src))
#define CP_COMMIT() asm volatile("cp.async.commit_group;" ::: "memory")
#define CP_WAIT(n)  asm volatile("cp.async.wait_group %0;" :: "n"(n) : "memory")

#define LDSM_X4(r0, r1, r2, r3, addr)                                          \
    asm volatile("ldmatrix.sync.aligned.m8n8.x4.shared.b16 {%0,%1,%2,%3}, [%4];" \
        : "=r"(r0), "=r"(r1), "=r"(r2), "=r"(r3) : "r"(addr))

#define LDSM_X4_T(r0, r1, r2, r3, addr)                                        \
    asm volatile("ldmatrix.sync.aligned.m8n8.x4.trans.shared.b16 {%0,%1,%2,%3}, [%4];" \
        : "=r"(r0), "=r"(r1), "=r"(r2), "=r"(r3) : "r"(addr))

#define MMA16816(d, a0, a1, a2, a3, b0, b1)                                    \
    asm volatile("mma.sync.aligned.m16n8k16.row.col.f32.bf16.bf16.f32 "        \
        "{%0,%1,%2,%3}, {%4,%5,%6,%7}, {%8,%9}, {%0,%1,%2,%3};"                \
        : "+f"((d)[0]), "+f"((d)[1]), "+f"((d)[2]), "+f"((d)[3])               \
        : "r"(a0), "r"(a1), "r"(a2), "r"(a3), "r"(b0), "r"(b1))

__device__ __forceinline__ uint32_t packbf(float lo, float hi) {
    uint32_t r;
    asm("cvt.rn.bf16x2.f32 %0, %1, %2;" : "=r"(r) : "f"(hi), "f"(lo));
    return r;
}

/* ================= GEMM mainloop (shared) =========================== */
#define KC      32
#define TILE_B  8192
#define STAGE_B (4 * TILE_B)
#define NSTAGE  3
#define GSM_TOTAL (NSTAGE * STAGE_B)   /* 96 KB */

__device__ __forceinline__ uint32_t tile_off(int r, int s) {
    return (uint32_t)((r & 63) * 128 + (((s | ((r >> 6) << 2)) ^ (r & 7)) << 4));
}

__device__ __forceinline__ void gemm_mainloop(
    const __nv_bfloat16* __restrict__ Ah, const __nv_bfloat16* __restrict__ Al,
    const __nv_bfloat16* __restrict__ Bh, const __nv_bfloat16* __restrict__ Bl,
    int N, int K, int m0, int n0, uint32_t sb, float acc[4][4][4])
{
    const int tid = threadIdx.x;
    const int wid = tid >> 5;
    const int lid = tid & 31;
    const int mw  = wid & 1;
    const int nw  = wid >> 1;

    const int r0 = tid >> 2;
    const int sg = tid & 3;
    const size_t rskip = (size_t)64 * K;
    const __nv_bfloat16* pAh = Ah + (size_t)(m0 + r0) * K + sg * 8;
    const __nv_bfloat16* pAl = Al + (size_t)(m0 + r0) * K + sg * 8;
    const uint32_t dA0 = tile_off(r0, sg);
    const uint32_t dA1 = tile_off(r0 + 64, sg);

    const int rb = tid >> 3;
    const int s1 = tid & 7;
    const __nv_bfloat16* pBh = Bh + (size_t)rb * N + n0 + s1 * 8;
    const __nv_bfloat16* pBl = Bl + (size_t)rb * N + n0 + s1 * 8;
    const uint32_t dB0 = (uint32_t)(rb * 256 + (((s1)     ^ (rb & 7)) << 4));
    const uint32_t dB1 = (uint32_t)(rb * 256 + (((s1 + 8) ^ (rb & 7)) << 4));

    const int nch = K / KC;

#define GEMM_LOAD_STAGE(stg, cidx) do {                                        \
        uint32_t _b = sb + (stg) * STAGE_B;                                    \
        size_t _ka = (size_t)(cidx) * KC;                                      \
        size_t _kb = (size_t)(cidx) * KC * N;                                  \
        CP_ASYNC16(_b + 0 * TILE_B + dA0, pAh + _ka);                          \
        CP_ASYNC16(_b + 0 * TILE_B + dA1, pAh + _ka + rskip);                  \
        CP_ASYNC16(_b + 1 * TILE_B + dA0, pAl + _ka);                          \
        CP_ASYNC16(_b + 1 * TILE_B + dA1, pAl + _ka + rskip);                  \
        CP_ASYNC16(_b + 2 * TILE_B + dB0, pBh + _kb);                          \
        CP_ASYNC16(_b + 2 * TILE_B + dB1, pBh + _kb + 64);                     \
        CP_ASYNC16(_b + 3 * TILE_B + dB0, pBl + _kb);                          \
        CP_ASYNC16(_b + 3 * TILE_B + dB1, pBl + _kb + 64);                     \
        CP_COMMIT();                                                           \
    } while (0)

    GEMM_LOAD_STAGE(0, 0);
    if (nch > 1) GEMM_LOAD_STAGE(1, 1);

    int st = 0;
    for (int c = 0; c < nch; c++) {
        if (c + 2 < nch) {
            GEMM_LOAD_STAGE((st + 2) % NSTAGE, c + 2);
            CP_WAIT(2);
        } else if (c + 1 < nch) {
            CP_WAIT(1);
        } else {
            CP_WAIT(0);
        }
        __syncthreads();

        const uint32_t tAh = sb + st * STAGE_B + 0 * TILE_B;
        const uint32_t tAl = sb + st * STAGE_B + 1 * TILE_B;
        const uint32_t tBh = sb + st * STAGE_B + 2 * TILE_B;
        const uint32_t tBl = sb + st * STAGE_B + 3 * TILE_B;

#pragma unroll
        for (int kb = 0; kb < KC / 16; kb++) {
            const int sseg = 2 * kb + (lid >> 4);
            uint32_t ah[4][4], al[4][4];
#pragma unroll
            for (int mf = 0; mf < 4; mf++) {
                int r = mw * 64 + mf * 16 + (lid & 15);
                uint32_t off = tile_off(r, sseg);
                LDSM_X4(ah[mf][0], ah[mf][1], ah[mf][2], ah[mf][3], tAh + off);
                LDSM_X4(al[mf][0], al[mf][1], al[mf][2], al[mf][3], tAl + off);
            }
            uint32_t bh[4][2], bl[4][2];
            {
                int br = kb * 16 + (lid & 7) + 8 * ((lid >> 3) & 1);
                uint32_t brow = (uint32_t)(br * 256);
                uint32_t bx   = (uint32_t)(br & 7) << 4;
#pragma unroll
                for (int nb = 0; nb < 2; nb++) {
                    uint32_t bs = (uint32_t)(nw * 4 + 2 * nb + (lid >> 4)) << 4;
                    uint32_t boff = brow + (bs ^ bx);
                    uint32_t b0, b1, b2, b3;
                    LDSM_X4_T(b0, b1, b2, b3, tBh + boff);
                    bh[2 * nb + 0][0] = b0; bh[2 * nb + 0][1] = b1;
                    bh[2 * nb + 1][0] = b2; bh[2 * nb + 1][1] = b3;
                    LDSM_X4_T(b0, b1, b2, b3, tBl + boff);
                    bl[2 * nb + 0][0] = b0; bl[2 * nb + 0][1] = b1;
                    bl[2 * nb + 1][0] = b2; bl[2 * nb + 1][1] = b3;
                }
            }
#pragma unroll
            for (int mf = 0; mf < 4; mf++)
#pragma unroll
                for (int j = 0; j < 4; j++)
                    MMA16816(acc[mf][j], ah[mf][0], ah[mf][1], ah[mf][2], ah[mf][3],
                             bh[j][0], bh[j][1]);
#pragma unroll
            for (int mf = 0; mf < 4; mf++)
#pragma unroll
                for (int j = 0; j < 4; j++)
                    MMA16816(acc[mf][j], ah[mf][0], ah[mf][1], ah[mf][2], ah[mf][3],
                             bl[j][0], bl[j][1]);
#pragma unroll
            for (int mf = 0; mf < 4; mf++)
#pragma unroll
                for (int j = 0; j < 4; j++)
                    MMA16816(acc[mf][j], al[mf][0], al[mf][1], al[mf][2], al[mf][3],
                             bh[j][0], bh[j][1]);
        }
        __syncthreads();
        st = (st + 1) % NSTAGE;
    }
}

/* ================= plain GEMM (out projection) ===================== */
__global__ __launch_bounds__(256, 2) void tc_gemm(
    const __nv_bfloat16* __restrict__ Ah, const __nv_bfloat16* __restrict__ Al,
    const __nv_bfloat16* __restrict__ Bh, const __nv_bfloat16* __restrict__ Bl,
    float* __restrict__ C, int M, int N, int K)
{
    extern __shared__ char smem[];
    const uint32_t sb = smem_u32(smem);
    const int lid = threadIdx.x & 31;
    const int wid = threadIdx.x >> 5;
    const int mw  = wid & 1;
    const int nw  = wid >> 1;
    const int m0  = blockIdx.y * 128;
    const int n0  = blockIdx.x * 128;

    float acc[4][4][4];
#pragma unroll
    for (int i = 0; i < 4; i++)
#pragma unroll
        for (int j = 0; j < 4; j++)
#pragma unroll
            for (int u = 0; u < 4; u++) acc[i][j][u] = 0.f;

    gemm_mainloop(Ah, Al, Bh, Bl, N, K, m0, n0, sb, acc);

#pragma unroll
    for (int mf = 0; mf < 4; mf++) {
        int rbase = m0 + mw * 64 + mf * 16 + (lid >> 2);
#pragma unroll
        for (int j = 0; j < 4; j++) {
            int col = n0 + nw * 32 + j * 8 + 2 * (lid & 3);
            *(float2*)&C[(size_t)rbase * N + col] =
                make_float2(acc[mf][j][0], acc[mf][j][1]);
            *(float2*)&C[(size_t)(rbase + 8) * N + col] =
                make_float2(acc[mf][j][2], acc[mf][j][3]);
        }
    }
}

/* ================= QKV GEMM with fused RMSNorm+RoPE+split ========== */
__global__ __launch_bounds__(256, 2) void tc_gemm_qkv(
    const __nv_bfloat16* __restrict__ Ah, const __nv_bfloat16* __restrict__ Al,
    const __nv_bfloat16* __restrict__ Bh, const __nv_bfloat16* __restrict__ Bl,
    const float* __restrict__ q_norm_w, const float* __restrict__ k_norm_w,
    int K)
{
    extern __shared__ char smem[];
    const uint32_t sb = smem_u32(smem);
    const int lid = threadIdx.x & 31;
    const int wid = threadIdx.x >> 5;
    const int mw  = wid & 1;
    const int nw  = wid >> 1;
    const int hidx = blockIdx.x;
    const int m0  = blockIdx.y * 128;
    const int n0  = hidx * 128;

    float acc[4][4][4];
#pragma unroll
    for (int i = 0; i < 4; i++)
#pragma unroll
        for (int j = 0; j < 4; j++)
#pragma unroll
            for (int u = 0; u < 4; u++) acc[i][j][u] = 0.f;

    gemm_mainloop(Ah, Al, Bh, Bl, QKV_N, K, m0, n0, sb, acc);

    const int cb = nw * 32 + 2 * (lid & 3);

    if (hidx >= NH + NKV) {
        const int hv = hidx - NH - NKV;
#pragma unroll
        for (int mf = 0; mf < 4; mf++) {
            int t0 = m0 + mw * 64 + mf * 16 + (lid >> 2);
#pragma unroll
            for (int j = 0; j < 4; j++) {
                int c = cb + j * 8;
                float a0 = acc[mf][j][0], a1 = acc[mf][j][1];
                float b0 = acc[mf][j][2], b1 = acc[mf][j][3];
                __nv_bfloat16 h0 = __float2bfloat16(a0), h1 = __float2bfloat16(a1);
                __nv_bfloat16 g0 = __float2bfloat16(b0), g1 = __float2bfloat16(b1);
                size_t iA = ((size_t)t0 * NKV + hv) * D + c;
                size_t iB = ((size_t)(t0 + 8) * NKV + hv) * D + c;
                *(uint32_t*)(g_vh + iA) = packbf(a0, a1);
                *(uint32_t*)(g_vl + iA) = packbf(a0 - __bfloat162float(h0),
                                                 a1 - __bfloat162float(h1));
                *(uint32_t*)(g_vh + iB) = packbf(b0, b1);
                *(uint32_t*)(g_vl + iB) = packbf(b0 - __bfloat162float(g0),
                                                 b1 - __bfloat162float(g1));
            }
        }
        return;
    }

    float* ssq  = (float*)smem;
    float* tile = (float*)smem + 512;

#pragma unroll
    for (int mf = 0; mf < 4; mf++) {
        float s0 = 0.f, s1 = 0.f;
#pragma unroll
        for (int j = 0; j < 4; j++) {
            s0 += acc[mf][j][0] * acc[mf][j][0] + acc[mf][j][1] * acc[mf][j][1];
            s1 += acc[mf][j][2] * acc[mf][j][2] + acc[mf][j][3] * acc[mf][j][3];
        }
        s0 += __shfl_xor_sync(0xFFFFFFFFu, s0, 1);
        s0 += __shfl_xor_sync(0xFFFFFFFFu, s0, 2);
        s1 += __shfl_xor_sync(0xFFFFFFFFu, s1, 1);
        s1 += __shfl_xor_sync(0xFFFFFFFFu, s1, 2);
        if ((lid & 3) == 0) {
            int rl = mw * 64 + mf * 16 + (lid >> 2);
            ssq[rl * 4 + nw] = s0;
            ssq[(rl + 8) * 4 + nw] = s1;
        }
    }
    __syncthreads();

    const float* w = (hidx < NH) ? q_norm_w : k_norm_w;
    float wv[4][2];
#pragma unroll
    for (int j = 0; j < 4; j++) {
        wv[j][0] = w[cb + j * 8];
        wv[j][1] = w[cb + j * 8 + 1];
    }
#pragma unroll
    for (int mf = 0; mf < 4; mf++) {
        int rl0 = mw * 64 + mf * 16 + (lid >> 2);
        int rl1 = rl0 + 8;
        float v0 = ssq[rl0 * 4 + 0] + ssq[rl0 * 4 + 1] + ssq[rl0 * 4 + 2] + ssq[rl0 * 4 + 3];
        float v1 = ssq[rl1 * 4 + 0] + ssq[rl1 * 4 + 1] + ssq[rl1 * 4 + 2] + ssq[rl1 * 4 + 3];
        float ri0 = rsqrtf(v0 * (1.f / (float)D) + 1e-6f);
        float ri1 = rsqrtf(v1 * (1.f / (float)D) + 1e-6f);
#pragma unroll
        for (int j = 0; j < 4; j++) {
            int c = cb + j * 8;
            tile[rl0 * 132 + c]     = acc[mf][j][0] * ri0 * wv[j][0];
            tile[rl0 * 132 + c + 1] = acc[mf][j][1] * ri0 * wv[j][1];
            tile[rl1 * 132 + c]     = acc[mf][j][2] * ri1 * wv[j][0];
            tile[rl1 * 132 + c + 1] = acc[mf][j][3] * ri1 * wv[j][1];
        }
    }
    __syncthreads();

    const float sc = (hidx < NH) ? 0.08838834764831845f : 1.0f;
#pragma unroll
    for (int mf = 0; mf < 4; mf++) {
#pragma unroll
        for (int half = 0; half < 2; half++) {
            int rl = mw * 64 + mf * 16 + (lid >> 2) + half * 8;
            int t  = m0 + rl;
#pragma unroll
            for (int j = 0; j < 4; j++) {
                int c = cb + j * 8;
                float y[2];
#pragma unroll
                for (int u = 0; u < 2; u++) {
                    int cc = c + u;
                    int dm = cc & 63;
                    float x = tile[rl * 132 + cc];
                    float p = tile[rl * 132 + (cc ^ 64)];
                    float cs = g_cos[(size_t)t * 64 + dm];
                    float sn = g_sin[(size_t)t * 64 + dm];
                    y[u] = (cc < 64) ? (x * cs - p * sn) : (x * cs + p * sn);
                    y[u] *= sc;
                }
                __nv_bfloat16 h0 = __float2bfloat16(y[0]);
                __nv_bfloat16 h1 = __float2bfloat16(y[1]);
                uint32_t hw = packbf(y[0], y[1]);
                uint32_t lw = packbf(y[0] - __bfloat162float(h0),
                                     y[1] - __bfloat162float(h1));
                if (hidx < NH) {
                    size_t o = ((size_t)t * NH + hidx) * D + c;
                    *(uint32_t*)(g_qh + o) = hw;
                    *(uint32_t*)(g_ql + o) = lw;
                } else {
                    size_t o = ((size_t)t * NKV + (hidx - NH)) * D + c;
                    *(uint32_t*)(g_kh + o) = hw;
                    *(uint32_t*)(g_kl + o) = lw;
                }
            }
        }
    }
}

/* ================= split conversion (wide: 8 elems/thread) ========= */
__global__ __launch_bounds__(256) void cvt_split(const float* __restrict__ x,
                                                 __nv_bfloat16* __restrict__ h,
                                                 __nv_bfloat16* __restrict__ l,
                                                 int n)
{
    int i = (blockIdx.x * 256 + threadIdx.x) * 8;
    if (i >= n) return;
    float4 v0 = *(const float4*)(x + i);
    float4 v1 = *(const float4*)(x + i + 4);
    float vv[8] = {v0.x, v0.y, v0.z, v0.w, v1.x, v1.y, v1.z, v1.w};
    __nv_bfloat16 hh[8], ll[8];
#pragma unroll
    for (int j = 0; j < 8; j++) {
        hh[j] = __float2bfloat16(vv[j]);
        ll[j] = __float2bfloat16(vv[j] - __bfloat162float(hh[j]));
    }
    *(uint4*)(h + i) = *(uint4*)hh;
    *(uint4*)(l + i) = *(uint4*)ll;
}

/* ---------------- trig tables --------------------------------------- */
__global__ void init_freq()
{
    int d = threadIdx.x;
    g_invfreq[d] = (float)(1.0 / pow(1000000.0, (double)d / (double)(D / 2)));
}

__global__ void init_trig(const int* __restrict__ positions)
{
    int t = blockIdx.x;
    int d = threadIdx.x;
    float ang = (float)positions[t] * g_invfreq[d];
    g_cos[(size_t)t * 64 + d] = cosf(ang);
    g_sin[(size_t)t * 64 + d] = sinf(ang);
}

/* ---------------- causal flash attention (R14 config, 632us) -------
   96KB smem, 128 threads, 2 CTAs/SM; hoisted cp.async addressing.    */
#define A_QH 0
#define A_QL 16384
#define A_KH 32768
#define A_KL 49152
#define A_VH 65536
#define A_VL 81920
#define ASM_TOTAL 98304

__global__ __launch_bounds__(128) void attn_kernel(int T_)
{
    extern __shared__ char asmem[];
    const uint32_t sb = smem_u32(asmem);

    const int h   = blockIdx.y;
    const int hk  = h >> 1;
    const int bi  = gridDim.x - 1 - blockIdx.x;
    const int m0  = bi * 64;
    const int tid = threadIdx.x;
    const int wid = tid >> 5;
    const int lid = tid & 31;
    const int wrow = wid * 16;

    const int lr = tid >> 4;
    const int ls = tid & 15;
    const uint32_t ldst = (uint32_t)(lr * 256 + ((ls ^ (lr & 7)) << 4));
    const size_t itstep_q  = (size_t)8 * NH * D;
    const size_t itstep_kv = (size_t)8 * NKV * D;
    const size_t qgb  = ((size_t)(m0 + lr) * NH + h) * D + ls * 8;
    const size_t kvgb = ((size_t)lr * NKV + hk) * D + ls * 8;

#pragma unroll
    for (int it = 0; it < 8; it++) {
        uint32_t off = ldst + it * 2048;
        size_t g = qgb + it * itstep_q;
        CP_ASYNC16(sb + A_QH + off, g_qh + g);
        CP_ASYNC16(sb + A_QL + off, g_ql + g);
    }
    CP_COMMIT();

    float o[16][4];
#pragma unroll
    for (int i = 0; i < 16; i++)
#pragma unroll
        for (int u = 0; u < 4; u++) o[i][u] = 0.f;

    const int r0g = m0 + wrow + (lid >> 2);
    const int r1g = r0g + 8;
    float mrow0 = -1e30f, mrow1 = -1e30f;
    float lsum0 = 0.f, lsum1 = 0.f;

    const int ntiles = bi + 1;
    for (int kt = 0; kt < ntiles; kt++) {
        const int k0 = kt * 64;
        __syncthreads();
        {
            const size_t gb = kvgb + (size_t)k0 * NKV * D;
#pragma unroll
            for (int it = 0; it < 8; it++) {
                uint32_t off = ldst + it * 2048;
                size_t g = gb + it * itstep_kv;
                CP_ASYNC16(sb + A_KH + off, g_kh + g);
                CP_ASYNC16(sb + A_KL + off, g_kl + g);
                CP_ASYNC16(sb + A_VH + off, g_vh + g);
                CP_ASYNC16(sb + A_VL + off, g_vl + g);
            }
        }
        CP_COMMIT();
        CP_WAIT(0);
        __syncthreads();

        /* ---- S = Q K^T (split-passes, independent accs) ---- */
        float sa[8][4];
#pragma unroll
        for (int nb = 0; nb < 8; nb++)
#pragma unroll
            for (int u = 0; u < 4; u++) sa[nb][u] = 0.f;

#pragma unroll
        for (int kb = 0; kb < 8; kb++) {
            int qr = wrow + (lid & 15);
            int qs = 2 * kb + (lid >> 4);
            uint32_t qoff = (uint32_t)(qr * 256 + ((qs ^ (qr & 7)) << 4));
            uint32_t qh0, qh1, qh2, qh3, ql0, ql1, ql2, ql3;
            LDSM_X4(qh0, qh1, qh2, qh3, sb + A_QH + qoff);
            LDSM_X4(ql0, ql1, ql2, ql3, sb + A_QL + qoff);

            uint32_t kh[4][4], kl[4][4];
#pragma unroll
            for (int nb16 = 0; nb16 < 4; nb16++) {
                int kr = nb16 * 16 + (lid & 15);
                int ks = 2 * kb + (lid >> 4);
                uint32_t koff = (uint32_t)(kr * 256 + ((ks ^ (kr & 7)) << 4));
                LDSM_X4(kh[nb16][0], kh[nb16][1], kh[nb16][2], kh[nb16][3], sb + A_KH + koff);
                LDSM_X4(kl[nb16][0], kl[nb16][1], kl[nb16][2], kl[nb16][3], sb + A_KL + koff);
            }
#pragma unroll
            for (int nb16 = 0; nb16 < 4; nb16++) {
                MMA16816(sa[2 * nb16 + 0], qh0, qh1, qh2, qh3, kh[nb16][0], kh[nb16][2]);
                MMA16816(sa[2 * nb16 + 1], qh0, qh1, qh2, qh3, kh[nb16][1], kh[nb16][3]);
            }
#pragma unroll
            for (int nb16 = 0; nb16 < 4; nb16++) {
                MMA16816(sa[2 * nb16 + 0], qh0, qh1, qh2, qh3, kl[nb16][0], kl[nb16][2]);
                MMA16816(sa[2 * nb16 + 1], qh0, qh1, qh2, qh3, kl[nb16][1], kl[nb16][3]);
            }
#pragma unroll
            for (int nb16 = 0; nb16 < 4; nb16++) {
                MMA16816(sa[2 * nb16 + 0], ql0, ql1, ql2, ql3, kh[nb16][0], kh[nb16][2]);
                MMA16816(sa[2 * nb16 + 1], ql0, ql1, ql2, ql3, kh[nb16][1], kh[nb16][3]);
            }
        }

        /* ---- mask + online softmax ---- */
        float mx0 = mrow0, mx1 = mrow1;
#pragma unroll
        for (int nb = 0; nb < 8; nb++) {
            int col = k0 + nb * 8 + 2 * (lid & 3);
            if (col > r0g)     sa[nb][0] = -1e30f;
            if (col + 1 > r0g) sa[nb][1] = -1e30f;
            if (col > r1g)     sa[nb][2] = -1e30f;
            if (col + 1 > r1g) sa[nb][3] = -1e30f;
            mx0 = fmaxf(mx0, fmaxf(sa[nb][0], sa[nb][1]));
            mx1 = fmaxf(mx1, fmaxf(sa[nb][2], sa[nb][3]));
        }
        mx0 = fmaxf(mx0, __shfl_xor_sync(0xFFFFFFFFu, mx0, 1));
        mx0 = fmaxf(mx0, __shfl_xor_sync(0xFFFFFFFFu, mx0, 2));
        mx1 = fmaxf(mx1, __shfl_xor_sync(0xFFFFFFFFu, mx1, 1));
        mx1 = fmaxf(mx1, __shfl_xor_sync(0xFFFFFFFFu, mx1, 2));

        float corr0 = __expf(mrow0 - mx0);
        float corr1 = __expf(mrow1 - mx1);
        mrow0 = mx0; mrow1 = mx1;

        float ps0 = 0.f, ps1 = 0.f;
#pragma unroll
        for (int nb = 0; nb < 8; nb++) {
            sa[nb][0] = __expf(sa[nb][0] - mx0);
            sa[nb][1] = __expf(sa[nb][1] - mx0);
            sa[nb][2] = __expf(sa[nb][2] - mx1);
            sa[nb][3] = __expf(sa[nb][3] - mx1);
            ps0 += sa[nb][0] + sa[nb][1];
            ps1 += sa[nb][2] + sa[nb][3];
        }
        ps0 += __shfl_xor_sync(0xFFFFFFFFu, ps0, 1);
        ps0 += __shfl_xor_sync(0xFFFFFFFFu, ps0, 2);
        ps1 += __shfl_xor_sync(0xFFFFFFFFu, ps1, 1);
        ps1 += __shfl_xor_sync(0xFFFFFFFFu, ps1, 2);
        lsum0 = lsum0 * corr0 + ps0;
        lsum1 = lsum1 * corr1 + ps1;

#pragma unroll
        for (int i = 0; i < 16; i++) {
            o[i][0] *= corr0; o[i][1] *= corr0;
            o[i][2] *= corr1; o[i][3] *= corr1;
        }

        /* ---- O += P V (dn pairs; split-passes over 4 accs) ---- */
#pragma unroll
        for (int jb = 0; jb < 4; jb++) {
            float p00 = sa[2 * jb][0],     p01 = sa[2 * jb][1];
            float p02 = sa[2 * jb][2],     p03 = sa[2 * jb][3];
            float p10 = sa[2 * jb + 1][0], p11 = sa[2 * jb + 1][1];
            float p12 = sa[2 * jb + 1][2], p13 = sa[2 * jb + 1][3];
            uint32_t ph0 = packbf(p00, p01), ph1 = packbf(p02, p03);
            uint32_t ph2 = packbf(p10, p11), ph3 = packbf(p12, p13);
            uint32_t pl0 = packbf(p00 - __bfloat162float(__float2bfloat16(p00)),
                                  p01 - __bfloat162float(__float2bfloat16(p01)));
            uint32_t pl1 = packbf(p02 - __bfloat162float(__float2bfloat16(p02)),
                                  p03 - __bfloat162float(__float2bfloat16(p03)));
            uint32_t pl2 = packbf(p10 - __bfloat162float(__float2bfloat16(p10)),
                                  p11 - __bfloat162float(__float2bfloat16(p11)));
            uint32_t pl3 = packbf(p12 - __bfloat162float(__float2bfloat16(p12)),
                                  p13 - __bfloat162float(__float2bfloat16(p13)));

            int m = lid >> 3;
            int vr = jb * 16 + (lid & 7) + 8 * (m & 1);
#pragma unroll
            for (int dp = 0; dp < 4; dp++) {
                int dn0 = 2 * dp, dn1 = 2 * dp + 1;
                int vs0 = 2 * dn0 + (m >> 1);
                int vs1 = 2 * dn1 + (m >> 1);
                uint32_t voff0 = (uint32_t)(vr * 256 + ((vs0 ^ (vr & 7)) << 4));
                uint32_t voff1 = (uint32_t)(vr * 256 + ((vs1 ^ (vr & 7)) << 4));
                uint32_t vA[4], vB[4], wA[4], wB[4];
                LDSM_X4_T(vA[0], vA[1], vA[2], vA[3], sb + A_VH + voff0);
                LDSM_X4_T(vB[0], vB[1], vB[2], vB[3], sb + A_VH + voff1);
                LDSM_X4_T(wA[0], wA[1], wA[2], wA[3], sb + A_VL + voff0);
                LDSM_X4_T(wB[0], wB[1], wB[2], wB[3], sb + A_VL + voff1);
                MMA16816(o[2 * dn0 + 0], ph0, ph1, ph2, ph3, vA[0], vA[1]);
                MMA16816(o[2 * dn0 + 1], ph0, ph1, ph2, ph3, vA[2], vA[3]);
                MMA16816(o[2 * dn1 + 0], ph0, ph1, ph2, ph3, vB[0], vB[1]);
                MMA16816(o[2 * dn1 + 1], ph0, ph1, ph2, ph3, vB[2], vB[3]);
                MMA16816(o[2 * dn0 + 0], ph0, ph1, ph2, ph3, wA[0], wA[1]);
                MMA16816(o[2 * dn0 + 1], ph0, ph1, ph2, ph3, wA[2], wA[3]);
                MMA16816(o[2 * dn1 + 0], ph0, ph1, ph2, ph3, wB[0], wB[1]);
                MMA16816(o[2 * dn1 + 1], ph0, ph1, ph2, ph3, wB[2], wB[3]);
                MMA16816(o[2 * dn0 + 0], pl0, pl1, pl2, pl3, vA[0], vA[1]);
                MMA16816(o[2 * dn0 + 1], pl0, pl1, pl2, pl3, vA[2], vA[3]);
                MMA16816(o[2 * dn1 + 0], pl0, pl1, pl2, pl3, vB[0], vB[1]);
                MMA16816(o[2 * dn1 + 1], pl0, pl1, pl2, pl3, vB[2], vB[3]);
            }
        }
    }

    const float inv0 = 1.f / lsum0;
    const float inv1 = 1.f / lsum1;
#pragma unroll
    for (int dn = 0; dn < 16; dn++) {
        int col = dn * 8 + 2 * (lid & 3);
        float a0 = o[dn][0] * inv0, a1 = o[dn][1] * inv0;
        float b0 = o[dn][2] * inv1, b1 = o[dn][3] * inv1;
        __nv_bfloat16 ha0 = __float2bfloat16(a0), ha1 = __float2bfloat16(a1);
        __nv_bfloat16 hb0 = __float2bfloat16(b0), hb1 = __float2bfloat16(b1);
        uint32_t hA = packbf(a0, a1);
        uint32_t lA = packbf(a0 - __bfloat162float(ha0), a1 - __bfloat162float(ha1));
        uint32_t hB = packbf(b0, b1);
        uint32_t lB = packbf(b0 - __bfloat162float(hb0), b1 - __bfloat162float(hb1));
        size_t iA = (size_t)r0g * (NH * D) + h * D + col;
        size_t iB = (size_t)r1g * (NH * D) + h * D + col;
        *(uint32_t*)(g_oth + iA) = hA;
        *(uint32_t*)(g_otl + iA) = lA;
        *(uint32_t*)(g_oth + iB) = hB;
        *(uint32_t*)(g_otl + iB) = lB;
    }
}

/* ---------------- launch -------------------------------------------- */
extern "C" void kernel_launch(void* const* d_in, const int* in_sizes, int n_in,
                              void* d_out, int out_size)
{
    const int*   positions = (const int*)d_in[0];
    const float* hidden    = (const float*)d_in[1];
    const float* w_qkv     = (const float*)d_in[2];
    const float* q_norm_w  = (const float*)d_in[3];
    const float* k_norm_w  = (const float*)d_in[4];
    const float* w_o       = (const float*)d_in[5];
    float*       out       = (float*)d_out;
    const int    T         = in_sizes[0];   /* 2048 */

    __nv_bfloat16 *ah, *al, *wqh, *wql, *oh, *ol, *woh, *wol;
    cudaGetSymbolAddress((void**)&ah,  g_ah);
    cudaGetSymbolAddress((void**)&al,  g_al);
    cudaGetSymbolAddress((void**)&wqh, g_wq_h);
    cudaGetSymbolAddress((void**)&wql, g_wq_l);
    cudaGetSymbolAddress((void**)&oh,  g_oth);
    cudaGetSymbolAddress((void**)&ol,  g_otl);
    cudaGetSymbolAddress((void**)&woh, g_wo_h);
    cudaGetSymbolAddress((void**)&wol, g_wo_l);

    cudaFuncSetAttribute(tc_gemm, cudaFuncAttributeMaxDynamicSharedMemorySize, GSM_TOTAL);
    cudaFuncSetAttribute(tc_gemm_qkv, cudaFuncAttributeMaxDynamicSharedMemorySize, GSM_TOTAL);
    cudaFuncSetAttribute(attn_kernel, cudaFuncAttributeMaxDynamicSharedMemorySize, ASM_TOTAL);

    /* 0) trig tables + straight splits (8 elems/thread) */
    init_freq<<<1, D / 2>>>();
    init_trig<<<T, 64>>>(positions);
    cvt_split<<<(T * HID) / 2048, 256>>>(hidden, ah, al, T * HID);
    cvt_split<<<(HID * QKV_N) / 2048, 256>>>(w_qkv, wqh, wql, HID * QKV_N);

    /* 1) QKV projection + fused RMSNorm/RoPE/split */
    {
        dim3 g(QKV_N / 128, T / 128);
        tc_gemm_qkv<<<g, 256, GSM_TOTAL>>>(ah, al, wqh, wql,
                                           q_norm_w, k_norm_w, HID);
    }

    /* 2) causal GQA flash attention */
    dim3 g3(T / 64, NH);
    attn_kernel<<<g3, 128, ASM_TOTAL>>>(T);

    /* 3) output projection */
    cvt_split<<<(HID * HID) / 2048, 256>>>(w_o, woh, wol, HID * HID);
    {
        dim3 g(HID / 128, T / 128);
        tc_gemm<<<g, 256, GSM_TOTAL>>>(oh, ol, woh, wol, out, T, HID, HID);
    }
}